// round 4
// baseline (speedup 1.0000x reference)
#include <cuda_runtime.h>
#include <math.h>

#define D 64
#define MAXN 100000
#define MAXE 1100000

// ---------------- static device scratch ----------------
__device__ float g_x  [MAXN * D];    // x_in = concat(u, v)
__device__ float g_su [MAXN * 128];  // per-node: [0..63]=x@Ui, [64..127]=x@Vj+bv
__device__ float g_xvi[MAXN * D];
__device__ float g_y  [MAXN * D];    // stage1 output
__device__ float g_y2 [MAXN * D];    // stage2 output
__device__ float g_stats1[2 * D];
__device__ float g_stats2[2 * D];
// CSR (edges sorted by destination)
__device__ int g_cnt[MAXN + 1];
__device__ int g_off[MAXN + 1];
__device__ int g_cur[MAXN];
__device__ int g_srcSorted[MAXE];
__device__ int g_bsum[512];

#define FMA4(ACC, A, B) do { (ACC).x += (A)*(B).x; (ACC).y += (A)*(B).y; \
                             (ACC).z += (A)*(B).z; (ACC).w += (A)*(B).w; } while(0)

// ================= CSR build =================
__global__ void hist_kernel(const int* __restrict__ ee, int nE)
{
    int e = blockIdx.x * blockDim.x + threadIdx.x;
    if (e < nE) atomicAdd(&g_cnt[ee[e]], 1);
}

// block-local exclusive scan of 256 counts into g_off; block total -> g_bsum
__global__ void scan_block_kernel(int n)
{
    __shared__ int sh[256];
    int tid = threadIdx.x;
    int i = blockIdx.x * 256 + tid;
    int v = (i < n) ? g_cnt[i] : 0;
    sh[tid] = v;
    __syncthreads();
    #pragma unroll
    for (int ofs = 1; ofs < 256; ofs <<= 1) {
        int x = (tid >= ofs) ? sh[tid - ofs] : 0;
        __syncthreads();
        sh[tid] += x;
        __syncthreads();
    }
    if (i < n) g_off[i] = sh[tid] - v;
    if (tid == 255) g_bsum[blockIdx.x] = sh[255];
}

// add prefix of block totals (computed inline by warp 0) to local offsets
__global__ void scan_add_kernel(int n)
{
    __shared__ int s_prefix;
    const int bid = blockIdx.x;
    if (threadIdx.x < 32) {
        int s = 0;
        for (int i = threadIdx.x; i < bid; i += 32) s += g_bsum[i];
        #pragma unroll
        for (int o = 16; o; o >>= 1) s += __shfl_down_sync(0xffffffffu, s, o);
        if (threadIdx.x == 0) s_prefix = s;
    }
    __syncthreads();
    int i = bid * 256 + threadIdx.x;
    if (i < n) {
        int o = g_off[i] + s_prefix;
        g_off[i] = o;
        g_cur[i] = o;
        if (i == n - 1) g_off[n] = o + g_cnt[i];
    }
}

__global__ void scatter_kernel(const int* __restrict__ es, const int* __restrict__ ee, int nE)
{
    int e = blockIdx.x * blockDim.x + threadIdx.x;
    if (e < nE) {
        int d = ee[e];
        int p = atomicAdd(&g_cur[d], 1);
        g_srcSorted[p] = es[e];
    }
}

// ================= fused 4-matrix GEMM: X @ [Ui|Uj|Vi|Vj] =================
#define XS_STRIDE 68
#define GEMM4_SMEM (64*256*4 + 64*XS_STRIDE*4)

template<bool BN>
__global__ void gemm4_kernel(const float* __restrict__ X,
                             const float* __restrict__ Ui, const float* __restrict__ Uj,
                             const float* __restrict__ Vi, const float* __restrict__ Vj,
                             const float* __restrict__ bu, const float* __restrict__ bv,
                             const float* __restrict__ stats, const float* __restrict__ gamma,
                             const float* __restrict__ beta,
                             float* __restrict__ su, float* __restrict__ y,
                             float* __restrict__ xvi,
                             int n)
{
    extern __shared__ float smem[];
    float* Ws = smem;              // [64][256]
    float* Xs = smem + 64 * 256;   // [64][XS_STRIDE]
    __shared__ float s_scale[64], s_shift[64];
    const int tid = threadIdx.x;
    const int rowBase = blockIdx.x * 64;

    if (BN) {
        if (tid < 64) {
            float fn = 1.f / (float)n;
            float mean = stats[tid] * fn;
            float var  = stats[64 + tid] * fn - mean * mean;
            float sc = gamma[tid] * rsqrtf(var + 1e-3f);
            s_scale[tid] = sc;
            s_shift[tid] = beta[tid] - mean * sc;
        }
        __syncthreads();
    }

    {
        const float* mats[4] = {Ui, Uj, Vi, Vj};
        #pragma unroll
        for (int m = 0; m < 4; m++) {
            const float4* src = (const float4*)mats[m];
            for (int i = tid; i < 1024; i += 256) {
                int k = i >> 4, j4 = i & 15;
                ((float4*)(Ws + k * 256 + m * 64))[j4] = src[k * 16 + j4];
            }
        }
        for (int i = tid; i < 1024; i += 256) {
            int r = i >> 4, c4 = i & 15;
            int row = rowBase + r;
            float4 v = make_float4(0.f, 0.f, 0.f, 0.f);
            if (row < n) v = ((const float4*)X)[row * 16 + c4];
            if (BN) {
                int c = c4 * 4;
                v.x = fmaxf(v.x * s_scale[c+0] + s_shift[c+0], 0.f);
                v.y = fmaxf(v.y * s_scale[c+1] + s_shift[c+1], 0.f);
                v.z = fmaxf(v.z * s_scale[c+2] + s_shift[c+2], 0.f);
                v.w = fmaxf(v.w * s_scale[c+3] + s_shift[c+3], 0.f);
            }
            *(float4*)(Xs + r * XS_STRIDE + c4 * 4) = v;
        }
    }
    __syncthreads();

    const int tx = tid & 15;
    const int ty = tid >> 4;
    float4 acc[4][4];
    #pragma unroll
    for (int r = 0; r < 4; r++)
        #pragma unroll
        for (int c = 0; c < 4; c++) acc[r][c] = make_float4(0.f, 0.f, 0.f, 0.f);

    #pragma unroll 8
    for (int k = 0; k < 64; k++) {
        float a0 = Xs[(ty * 4 + 0) * XS_STRIDE + k];
        float a1 = Xs[(ty * 4 + 1) * XS_STRIDE + k];
        float a2 = Xs[(ty * 4 + 2) * XS_STRIDE + k];
        float a3 = Xs[(ty * 4 + 3) * XS_STRIDE + k];
        const float4* wrow = (const float4*)(Ws + k * 256);
        float4 b0 = wrow[tx * 4 + 0];
        float4 b1 = wrow[tx * 4 + 1];
        float4 b2 = wrow[tx * 4 + 2];
        float4 b3 = wrow[tx * 4 + 3];
        FMA4(acc[0][0], a0, b0); FMA4(acc[0][1], a0, b1); FMA4(acc[0][2], a0, b2); FMA4(acc[0][3], a0, b3);
        FMA4(acc[1][0], a1, b0); FMA4(acc[1][1], a1, b1); FMA4(acc[1][2], a1, b2); FMA4(acc[1][3], a1, b3);
        FMA4(acc[2][0], a2, b0); FMA4(acc[2][1], a2, b1); FMA4(acc[2][2], a2, b2); FMA4(acc[2][3], a2, b3);
        FMA4(acc[3][0], a3, b0); FMA4(acc[3][1], a3, b1); FMA4(acc[3][2], a3, b2); FMA4(acc[3][3], a3, b3);
    }

    // m: 0 -> su[+0] (x@Ui); 1 -> y (+bu); 2 -> xvi; 3 -> su[+64] (x@Vj +bv)
    const int m = tx >> 2;
    const int ccb = (tx & 3) * 16;
    float* dst; const float* bias; int stride;
    if      (m == 0) { dst = su + ccb;      bias = nullptr; stride = 128; }
    else if (m == 1) { dst = y + ccb;       bias = bu;      stride = 64;  }
    else if (m == 2) { dst = xvi + ccb;     bias = nullptr; stride = 64;  }
    else             { dst = su + 64 + ccb; bias = bv;      stride = 128; }

    float4 bb[4];
    #pragma unroll
    for (int c = 0; c < 4; c++) {
        if (bias) bb[c] = ((const float4*)bias)[(ccb >> 2) + c];
        else      bb[c] = make_float4(0.f, 0.f, 0.f, 0.f);
    }

    #pragma unroll
    for (int r = 0; r < 4; r++) {
        int row = rowBase + ty * 4 + r;
        if (row < n) {
            float4* o = (float4*)(dst + (size_t)row * stride);
            #pragma unroll
            for (int c = 0; c < 4; c++) {
                float4 v = acc[r][c];
                v.x += bb[c].x; v.y += bb[c].y; v.z += bb[c].z; v.w += bb[c].w;
                o[c] = v;
            }
        }
    }
}

// ================= per-node aggregation: 1 warp per node =================
// lanes 0-15 / 16-31 = two edge slots over the same node; combined via shfl.
__device__ __forceinline__ float4 sig_mul(float4 vi, float4 vj, float4 ui)
{
    float4 r;
    r.x = ui.x / (1.f + __expf(-(vi.x + vj.x)));
    r.y = ui.y / (1.f + __expf(-(vi.y + vj.y)));
    r.z = ui.z / (1.f + __expf(-(vi.z + vj.z)));
    r.w = ui.w / (1.f + __expf(-(vi.w + vj.w)));
    return r;
}

__global__ void agg_kernel(const float* __restrict__ xvi, const float* __restrict__ su,
                           float* __restrict__ y, float* __restrict__ stats, int n)
{
    __shared__ float s_sum[64], s_sum2[64];
    const int tid = threadIdx.x;
    if (tid < 64) { s_sum[tid] = 0.f; s_sum2[tid] = 0.f; }
    __syncthreads();

    const int warp = tid >> 5;
    const int lane = tid & 31;
    const int half = lane >> 4;
    const int l4   = lane & 15;
    const int node = blockIdx.x * 8 + warp;

    if (node < n) {
        float4 vi = ((const float4*)(xvi + (size_t)node * 64))[l4];
        float4 acc = make_float4(0.f, 0.f, 0.f, 0.f);
        const int p0 = g_off[node];
        const int p1 = g_off[node + 1];

        int pp = p0 + half;
        // unrolled x2: this half handles pp, pp+2 (4 edges in flight per warp)
        for (; pp + 2 < p1; pp += 4) {
            int bA = __ldg(g_srcSorted + pp);
            int bB = __ldg(g_srcSorted + pp + 2);
            const float4* sA = (const float4*)(su + (size_t)bA * 128);
            const float4* sB = (const float4*)(su + (size_t)bB * 128);
            float4 uiA = __ldg(sA + l4);
            float4 vjA = __ldg(sA + 16 + l4);
            float4 uiB = __ldg(sB + l4);
            float4 vjB = __ldg(sB + 16 + l4);
            float4 mA = sig_mul(vi, vjA, uiA);
            float4 mB = sig_mul(vi, vjB, uiB);
            acc.x += mA.x + mB.x;
            acc.y += mA.y + mB.y;
            acc.z += mA.z + mB.z;
            acc.w += mA.w + mB.w;
        }
        for (; pp < p1; pp += 2) {
            int b = __ldg(g_srcSorted + pp);
            const float4* sb = (const float4*)(su + (size_t)b * 128);
            float4 ui = __ldg(sb + l4);
            float4 vj = __ldg(sb + 16 + l4);
            float4 m = sig_mul(vi, vj, ui);
            acc.x += m.x; acc.y += m.y; acc.z += m.z; acc.w += m.w;
        }

        // combine the two halves
        acc.x += __shfl_xor_sync(0xffffffffu, acc.x, 16);
        acc.y += __shfl_xor_sync(0xffffffffu, acc.y, 16);
        acc.z += __shfl_xor_sync(0xffffffffu, acc.z, 16);
        acc.w += __shfl_xor_sync(0xffffffffu, acc.w, 16);

        if (half == 0) {
            float4 base = ((const float4*)(y + (size_t)node * 64))[l4];  // x@Uj + bu
            acc.x += base.x; acc.y += base.y; acc.z += base.z; acc.w += base.w;
            ((float4*)(y + (size_t)node * 64))[l4] = acc;

            int c = l4 * 4;
            atomicAdd(&s_sum[c + 0], acc.x);  atomicAdd(&s_sum2[c + 0], acc.x * acc.x);
            atomicAdd(&s_sum[c + 1], acc.y);  atomicAdd(&s_sum2[c + 1], acc.y * acc.y);
            atomicAdd(&s_sum[c + 2], acc.z);  atomicAdd(&s_sum2[c + 2], acc.z * acc.z);
            atomicAdd(&s_sum[c + 3], acc.w);  atomicAdd(&s_sum2[c + 3], acc.w * acc.w);
        }
    }
    __syncthreads();
    if (tid < 64) {
        atomicAdd(stats + tid,      s_sum[tid]);
        atomicAdd(stats + 64 + tid, s_sum2[tid]);
    }
}

// ================= final: out = relu( BN2(y2) + x_in @ R ) =================
__global__ void final_kernel(const float* __restrict__ X, const float* __restrict__ R,
                             const float* __restrict__ y2, const float* __restrict__ stats,
                             const float* __restrict__ gamma, const float* __restrict__ beta,
                             float* __restrict__ out, int n)
{
    __shared__ float Rs[64 * 64];
    __shared__ float Xs[64 * XS_STRIDE];
    const int tid = threadIdx.x;
    const int rowBase = blockIdx.x * 64;

    for (int i = tid; i < 1024; i += 256)
        ((float4*)Rs)[i] = ((const float4*)R)[i];
    for (int i = tid; i < 1024; i += 256) {
        int r = i >> 4, c4 = i & 15;
        int row = rowBase + r;
        float4 v = make_float4(0.f, 0.f, 0.f, 0.f);
        if (row < n) v = ((const float4*)X)[row * 16 + c4];
        *(float4*)(Xs + r * XS_STRIDE + c4 * 4) = v;
    }
    __syncthreads();

    const int tx = tid & 15;
    const int ty = tid >> 4;
    float4 acc[4];
    #pragma unroll
    for (int r = 0; r < 4; r++) acc[r] = make_float4(0.f, 0.f, 0.f, 0.f);

    #pragma unroll 8
    for (int k = 0; k < 64; k++) {
        float a0 = Xs[(ty * 4 + 0) * XS_STRIDE + k];
        float a1 = Xs[(ty * 4 + 1) * XS_STRIDE + k];
        float a2 = Xs[(ty * 4 + 2) * XS_STRIDE + k];
        float a3 = Xs[(ty * 4 + 3) * XS_STRIDE + k];
        float4 b = ((const float4*)(Rs + k * 64))[tx];
        FMA4(acc[0], a0, b);
        FMA4(acc[1], a1, b);
        FMA4(acc[2], a2, b);
        FMA4(acc[3], a3, b);
    }

    float fn = 1.f / (float)n;
    float scale[4], shift[4];
    #pragma unroll
    for (int j = 0; j < 4; j++) {
        int c = tx * 4 + j;
        float mean = stats[c] * fn;
        float var  = stats[64 + c] * fn - mean * mean;
        float sc = gamma[c] * rsqrtf(var + 1e-3f);
        scale[j] = sc;
        shift[j] = beta[c] - mean * sc;
    }

    #pragma unroll
    for (int r = 0; r < 4; r++) {
        int row = rowBase + ty * 4 + r;
        if (row < n) {
            float4 yv = ((const float4*)(y2 + (size_t)row * 64))[tx];
            float o0 = acc[r].x + yv.x * scale[0] + shift[0];
            float o1 = acc[r].y + yv.y * scale[1] + shift[1];
            float o2 = acc[r].z + yv.z * scale[2] + shift[2];
            float o3 = acc[r].w + yv.w * scale[3] + shift[3];
            float4 ov;
            ov.x = o0 > 0.f ? o0 : 0.f;
            ov.y = o1 > 0.f ? o1 : 0.f;
            ov.z = o2 > 0.f ? o2 : 0.f;
            ov.w = o3 > 0.f ? o3 : 0.f;
            ((float4*)(out + (size_t)row * 64))[tx] = ov;
        }
    }
}

// ================= host =================
extern "C" void kernel_launch(void* const* d_in, const int* in_sizes, int n_in,
                              void* d_out, int out_size)
{
    const float* u   = (const float*)d_in[0];
    const float* v   = (const float*)d_in[1];
    const int*   es  = (const int*)  d_in[2];
    const int*   ee  = (const int*)  d_in[3];
    const float* Ui1 = (const float*)d_in[4];
    const float* Uj1 = (const float*)d_in[5];
    const float* Vi1 = (const float*)d_in[6];
    const float* Vj1 = (const float*)d_in[7];
    const float* bu1 = (const float*)d_in[8];
    const float* bv1 = (const float*)d_in[9];
    const float* Ui2 = (const float*)d_in[10];
    const float* Uj2 = (const float*)d_in[11];
    const float* Vi2 = (const float*)d_in[12];
    const float* Vj2 = (const float*)d_in[13];
    const float* bu2 = (const float*)d_in[14];
    const float* bv2 = (const float*)d_in[15];
    const float* R   = (const float*)d_in[16];
    const float* gamma1 = (const float*)d_in[17];
    const float* beta1  = (const float*)d_in[18];
    const float* gamma2 = (const float*)d_in[19];
    const float* beta2  = (const float*)d_in[20];

    const int nU = in_sizes[0] / 64;
    const int nV = in_sizes[1] / 64;
    const int n  = nU + nV;
    const int nE = in_sizes[2];

    float *px, *psu, *pxvi, *py, *py2, *pst1, *pst2;
    int *pcnt;
    cudaGetSymbolAddress((void**)&px,   g_x);
    cudaGetSymbolAddress((void**)&psu,  g_su);
    cudaGetSymbolAddress((void**)&pxvi, g_xvi);
    cudaGetSymbolAddress((void**)&py,   g_y);
    cudaGetSymbolAddress((void**)&py2,  g_y2);
    cudaGetSymbolAddress((void**)&pst1, g_stats1);
    cudaGetSymbolAddress((void**)&pst2, g_stats2);
    cudaGetSymbolAddress((void**)&pcnt, g_cnt);

    cudaFuncSetAttribute(gemm4_kernel<false>, cudaFuncAttributeMaxDynamicSharedMemorySize, GEMM4_SMEM);
    cudaFuncSetAttribute(gemm4_kernel<true>,  cudaFuncAttributeMaxDynamicSharedMemorySize, GEMM4_SMEM);

    // x_in = concat(u, v)
    cudaMemcpyAsync(px,                   u, (size_t)nU * 64 * sizeof(float), cudaMemcpyDeviceToDevice);
    cudaMemcpyAsync(px + (size_t)nU * 64, v, (size_t)nV * 64 * sizeof(float), cudaMemcpyDeviceToDevice);
    cudaMemsetAsync(pcnt, 0, (MAXN + 1) * sizeof(int));
    cudaMemsetAsync(pst1, 0, 2 * D * sizeof(float));
    cudaMemsetAsync(pst2, 0, 2 * D * sizeof(float));

    const int eb = (nE + 255) / 256;
    const int nb = (n + 255) / 256;
    const int gemmBlocks = (n + 63) / 64;
    const int aggBlocks  = (n + 7) / 8;

    // CSR build part 1 (3 kernels), then gemm4 as the 4th launch (ncu captures #4)
    hist_kernel<<<eb, 256>>>(ee, nE);
    scan_block_kernel<<<nb, 256>>>(n);
    scan_add_kernel<<<nb, 256>>>(n);

    // ---- stage 1 GEMM (launch #4 — profiled) ----
    gemm4_kernel<false><<<gemmBlocks, 256, GEMM4_SMEM>>>(px, Ui1, Uj1, Vi1, Vj1, bu1, bv1,
                                                         nullptr, nullptr, nullptr,
                                                         psu, py, pxvi, n);
    scatter_kernel<<<eb, 256>>>(es, ee, nE);
    agg_kernel<<<aggBlocks, 256>>>(pxvi, psu, py, pst1, n);

    // ---- stage 2 (BN1+ReLU fused into X load) ----
    gemm4_kernel<true><<<gemmBlocks, 256, GEMM4_SMEM>>>(py, Ui2, Uj2, Vi2, Vj2, bu2, bv2,
                                                        pst1, gamma1, beta1,
                                                        psu, py2, pxvi, n);
    agg_kernel<<<aggBlocks, 256>>>(pxvi, psu, py2, pst2, n);

    // ---- final: relu(BN2(y2) + x_in @ R) ----
    final_kernel<<<gemmBlocks, 256>>>(px, R, py2, pst2, gamma2, beta2, (float*)d_out, n);
}

// round 5
// speedup vs baseline: 1.5850x; 1.5850x over previous
#include <cuda_runtime.h>
#include <math.h>

#define D 64
#define MAXN 100000
#define MAXE 1100000

// ---------------- static device scratch ----------------
__device__ float g_x  [MAXN * D];    // x_in = concat(u, v)
__device__ float g_su [MAXN * 128];  // per-node: [0..63]=x@Ui, [64..127]=x@Vj+bv
__device__ float g_xvi[MAXN * D];
__device__ float g_y  [MAXN * D];    // stage1 output
__device__ float g_y2 [MAXN * D];    // stage2 output
__device__ float g_stats1[2 * D];
__device__ float g_stats2[2 * D];
// CSR (edges sorted by destination)
__device__ int g_cnt[MAXN + 1];
__device__ int g_off[MAXN + 1];
__device__ int g_cur[MAXN];
__device__ int g_srcSorted[MAXE];
__device__ int g_bsum[512];

#define FMA4(ACC, A, B) do { (ACC).x += (A)*(B).x; (ACC).y += (A)*(B).y; \
                             (ACC).z += (A)*(B).z; (ACC).w += (A)*(B).w; } while(0)

// ================= CSR build =================
__global__ void hist_kernel(const int* __restrict__ ee, int nE)
{
    int e = blockIdx.x * blockDim.x + threadIdx.x;
    if (e < nE) atomicAdd(&g_cnt[ee[e]], 1);
}

__global__ void scan_block_kernel(int n)
{
    __shared__ int sh[256];
    int tid = threadIdx.x;
    int i = blockIdx.x * 256 + tid;
    int v = (i < n) ? g_cnt[i] : 0;
    sh[tid] = v;
    __syncthreads();
    #pragma unroll
    for (int ofs = 1; ofs < 256; ofs <<= 1) {
        int x = (tid >= ofs) ? sh[tid - ofs] : 0;
        __syncthreads();
        sh[tid] += x;
        __syncthreads();
    }
    if (i < n) g_off[i] = sh[tid] - v;
    if (tid == 255) g_bsum[blockIdx.x] = sh[255];
}

__global__ void scan_add_kernel(int n)
{
    __shared__ int s_prefix;
    const int bid = blockIdx.x;
    if (threadIdx.x < 32) {
        int s = 0;
        for (int i = threadIdx.x; i < bid; i += 32) s += g_bsum[i];
        #pragma unroll
        for (int o = 16; o; o >>= 1) s += __shfl_down_sync(0xffffffffu, s, o);
        if (threadIdx.x == 0) s_prefix = s;
    }
    __syncthreads();
    int i = bid * 256 + threadIdx.x;
    if (i < n) {
        int o = g_off[i] + s_prefix;
        g_off[i] = o;
        g_cur[i] = o;
        if (i == n - 1) g_off[n] = o + g_cnt[i];
    }
}

__global__ void scatter_kernel(const int* __restrict__ es, const int* __restrict__ ee, int nE)
{
    int e = blockIdx.x * blockDim.x + threadIdx.x;
    if (e < nE) {
        int d = ee[e];
        int p = atomicAdd(&g_cur[d], 1);
        g_srcSorted[p] = es[e];
    }
}

// ================= fused 4-matrix GEMM: X @ [Ui|Uj|Vi|Vj] =================
// Thread tx owns columns 4tx..4tx+3 of EACH matrix (float4 index tx+16c in the
// 256-wide combined W) -> conflict-free LDS.128 (lane word = 4*tx).
#define XS_STRIDE 68
#define GEMM4_SMEM (64*256*4 + 64*XS_STRIDE*4)

template<bool BN>
__global__ void gemm4_kernel(const float* __restrict__ X,
                             const float* __restrict__ Ui, const float* __restrict__ Uj,
                             const float* __restrict__ Vi, const float* __restrict__ Vj,
                             const float* __restrict__ bu, const float* __restrict__ bv,
                             const float* __restrict__ stats, const float* __restrict__ gamma,
                             const float* __restrict__ beta,
                             float* __restrict__ su, float* __restrict__ y,
                             float* __restrict__ xvi,
                             int n)
{
    extern __shared__ float smem[];
    float* Ws = smem;              // [64][256]
    float* Xs = smem + 64 * 256;   // [64][XS_STRIDE]
    __shared__ float s_scale[64], s_shift[64];
    const int tid = threadIdx.x;
    const int rowBase = blockIdx.x * 64;

    if (BN) {
        if (tid < 64) {
            float fn = 1.f / (float)n;
            float mean = stats[tid] * fn;
            float var  = stats[64 + tid] * fn - mean * mean;
            float sc = gamma[tid] * rsqrtf(var + 1e-3f);
            s_scale[tid] = sc;
            s_shift[tid] = beta[tid] - mean * sc;
        }
        __syncthreads();
    }

    {
        const float* mats[4] = {Ui, Uj, Vi, Vj};
        #pragma unroll
        for (int m = 0; m < 4; m++) {
            const float4* src = (const float4*)mats[m];
            for (int i = tid; i < 1024; i += 256) {
                int k = i >> 4, j4 = i & 15;
                ((float4*)(Ws + k * 256 + m * 64))[j4] = src[k * 16 + j4];
            }
        }
        for (int i = tid; i < 1024; i += 256) {
            int r = i >> 4, c4 = i & 15;
            int row = rowBase + r;
            float4 v = make_float4(0.f, 0.f, 0.f, 0.f);
            if (row < n) v = ((const float4*)X)[row * 16 + c4];
            if (BN) {
                int c = c4 * 4;
                v.x = fmaxf(v.x * s_scale[c+0] + s_shift[c+0], 0.f);
                v.y = fmaxf(v.y * s_scale[c+1] + s_shift[c+1], 0.f);
                v.z = fmaxf(v.z * s_scale[c+2] + s_shift[c+2], 0.f);
                v.w = fmaxf(v.w * s_scale[c+3] + s_shift[c+3], 0.f);
            }
            *(float4*)(Xs + r * XS_STRIDE + c4 * 4) = v;
        }
    }
    __syncthreads();

    const int tx = tid & 15;
    const int ty = tid >> 4;
    float4 acc[4][4];   // [row r][matrix c]
    #pragma unroll
    for (int r = 0; r < 4; r++)
        #pragma unroll
        for (int c = 0; c < 4; c++) acc[r][c] = make_float4(0.f, 0.f, 0.f, 0.f);

    #pragma unroll 8
    for (int k = 0; k < 64; k++) {
        float a0 = Xs[(ty * 4 + 0) * XS_STRIDE + k];
        float a1 = Xs[(ty * 4 + 1) * XS_STRIDE + k];
        float a2 = Xs[(ty * 4 + 2) * XS_STRIDE + k];
        float a3 = Xs[(ty * 4 + 3) * XS_STRIDE + k];
        const float4* wrow = (const float4*)(Ws + k * 256);
        float4 b0 = wrow[tx];        // matrix 0, cols 4tx..4tx+3 (conflict-free)
        float4 b1 = wrow[tx + 16];   // matrix 1
        float4 b2 = wrow[tx + 32];   // matrix 2
        float4 b3 = wrow[tx + 48];   // matrix 3
        FMA4(acc[0][0], a0, b0); FMA4(acc[0][1], a0, b1); FMA4(acc[0][2], a0, b2); FMA4(acc[0][3], a0, b3);
        FMA4(acc[1][0], a1, b0); FMA4(acc[1][1], a1, b1); FMA4(acc[1][2], a1, b2); FMA4(acc[1][3], a1, b3);
        FMA4(acc[2][0], a2, b0); FMA4(acc[2][1], a2, b1); FMA4(acc[2][2], a2, b2); FMA4(acc[2][3], a2, b3);
        FMA4(acc[3][0], a3, b0); FMA4(acc[3][1], a3, b1); FMA4(acc[3][2], a3, b2); FMA4(acc[3][3], a3, b3);
    }

    // biases for this thread's float4 column slice
    float4 bu4 = ((const float4*)bu)[tx];
    float4 bv4 = ((const float4*)bv)[tx];

    #pragma unroll
    for (int r = 0; r < 4; r++) {
        int row = rowBase + ty * 4 + r;
        if (row < n) {
            // matrix 0 -> su[+0] (x@Ui)
            ((float4*)(su + (size_t)row * 128))[tx] = acc[r][0];
            // matrix 1 -> y (x@Uj + bu)
            float4 v1 = acc[r][1];
            v1.x += bu4.x; v1.y += bu4.y; v1.z += bu4.z; v1.w += bu4.w;
            ((float4*)(y + (size_t)row * 64))[tx] = v1;
            // matrix 2 -> xvi
            ((float4*)(xvi + (size_t)row * 64))[tx] = acc[r][2];
            // matrix 3 -> su[+64] (x@Vj + bv)
            float4 v3 = acc[r][3];
            v3.x += bv4.x; v3.y += bv4.y; v3.z += bv4.z; v3.w += bv4.w;
            ((float4*)(su + (size_t)row * 128 + 64))[tx] = v3;
        }
    }
}

// ================= per-node aggregation: 1 warp per node =================
__device__ __forceinline__ float4 sig_mul(float4 vi, float4 vj, float4 ui)
{
    float4 r;
    r.x = ui.x / (1.f + __expf(-(vi.x + vj.x)));
    r.y = ui.y / (1.f + __expf(-(vi.y + vj.y)));
    r.z = ui.z / (1.f + __expf(-(vi.z + vj.z)));
    r.w = ui.w / (1.f + __expf(-(vi.w + vj.w)));
    return r;
}

__global__ void agg_kernel(const float* __restrict__ xvi, const float* __restrict__ su,
                           float* __restrict__ y, float* __restrict__ stats, int n)
{
    __shared__ float s_sum[64], s_sum2[64];
    const int tid = threadIdx.x;
    if (tid < 64) { s_sum[tid] = 0.f; s_sum2[tid] = 0.f; }
    __syncthreads();

    const int warp = tid >> 5;
    const int lane = tid & 31;
    const int half = lane >> 4;
    const int l4   = lane & 15;
    const int node = blockIdx.x * 8 + warp;

    if (node < n) {
        float4 vi = ((const float4*)(xvi + (size_t)node * 64))[l4];
        float4 acc = make_float4(0.f, 0.f, 0.f, 0.f);
        const int p0 = g_off[node];
        const int p1 = g_off[node + 1];

        int pp = p0 + half;
        for (; pp + 2 < p1; pp += 4) {
            int bA = __ldg(g_srcSorted + pp);
            int bB = __ldg(g_srcSorted + pp + 2);
            const float4* sA = (const float4*)(su + (size_t)bA * 128);
            const float4* sB = (const float4*)(su + (size_t)bB * 128);
            float4 uiA = __ldg(sA + l4);
            float4 vjA = __ldg(sA + 16 + l4);
            float4 uiB = __ldg(sB + l4);
            float4 vjB = __ldg(sB + 16 + l4);
            float4 mA = sig_mul(vi, vjA, uiA);
            float4 mB = sig_mul(vi, vjB, uiB);
            acc.x += mA.x + mB.x;
            acc.y += mA.y + mB.y;
            acc.z += mA.z + mB.z;
            acc.w += mA.w + mB.w;
        }
        for (; pp < p1; pp += 2) {
            int b = __ldg(g_srcSorted + pp);
            const float4* sb = (const float4*)(su + (size_t)b * 128);
            float4 ui = __ldg(sb + l4);
            float4 vj = __ldg(sb + 16 + l4);
            float4 m = sig_mul(vi, vj, ui);
            acc.x += m.x; acc.y += m.y; acc.z += m.z; acc.w += m.w;
        }

        acc.x += __shfl_xor_sync(0xffffffffu, acc.x, 16);
        acc.y += __shfl_xor_sync(0xffffffffu, acc.y, 16);
        acc.z += __shfl_xor_sync(0xffffffffu, acc.z, 16);
        acc.w += __shfl_xor_sync(0xffffffffu, acc.w, 16);

        if (half == 0) {
            float4 base = ((const float4*)(y + (size_t)node * 64))[l4];
            acc.x += base.x; acc.y += base.y; acc.z += base.z; acc.w += base.w;
            ((float4*)(y + (size_t)node * 64))[l4] = acc;

            int c = l4 * 4;
            atomicAdd(&s_sum[c + 0], acc.x);  atomicAdd(&s_sum2[c + 0], acc.x * acc.x);
            atomicAdd(&s_sum[c + 1], acc.y);  atomicAdd(&s_sum2[c + 1], acc.y * acc.y);
            atomicAdd(&s_sum[c + 2], acc.z);  atomicAdd(&s_sum2[c + 2], acc.z * acc.z);
            atomicAdd(&s_sum[c + 3], acc.w);  atomicAdd(&s_sum2[c + 3], acc.w * acc.w);
        }
    }
    __syncthreads();
    if (tid < 64) {
        atomicAdd(stats + tid,      s_sum[tid]);
        atomicAdd(stats + 64 + tid, s_sum2[tid]);
    }
}

// ================= final: out = relu( BN2(y2) + x_in @ R ) =================
__global__ void final_kernel(const float* __restrict__ X, const float* __restrict__ R,
                             const float* __restrict__ y2, const float* __restrict__ stats,
                             const float* __restrict__ gamma, const float* __restrict__ beta,
                             float* __restrict__ out, int n)
{
    __shared__ float Rs[64 * 64];
    __shared__ float Xs[64 * XS_STRIDE];
    const int tid = threadIdx.x;
    const int rowBase = blockIdx.x * 64;

    for (int i = tid; i < 1024; i += 256)
        ((float4*)Rs)[i] = ((const float4*)R)[i];
    for (int i = tid; i < 1024; i += 256) {
        int r = i >> 4, c4 = i & 15;
        int row = rowBase + r;
        float4 v = make_float4(0.f, 0.f, 0.f, 0.f);
        if (row < n) v = ((const float4*)X)[row * 16 + c4];
        *(float4*)(Xs + r * XS_STRIDE + c4 * 4) = v;
    }
    __syncthreads();

    const int tx = tid & 15;
    const int ty = tid >> 4;
    float4 acc[4];
    #pragma unroll
    for (int r = 0; r < 4; r++) acc[r] = make_float4(0.f, 0.f, 0.f, 0.f);

    #pragma unroll 8
    for (int k = 0; k < 64; k++) {
        float a0 = Xs[(ty * 4 + 0) * XS_STRIDE + k];
        float a1 = Xs[(ty * 4 + 1) * XS_STRIDE + k];
        float a2 = Xs[(ty * 4 + 2) * XS_STRIDE + k];
        float a3 = Xs[(ty * 4 + 3) * XS_STRIDE + k];
        float4 b = ((const float4*)(Rs + k * 64))[tx];
        FMA4(acc[0], a0, b);
        FMA4(acc[1], a1, b);
        FMA4(acc[2], a2, b);
        FMA4(acc[3], a3, b);
    }

    float fn = 1.f / (float)n;
    float scale[4], shift[4];
    #pragma unroll
    for (int j = 0; j < 4; j++) {
        int c = tx * 4 + j;
        float mean = stats[c] * fn;
        float var  = stats[64 + c] * fn - mean * mean;
        float sc = gamma[c] * rsqrtf(var + 1e-3f);
        scale[j] = sc;
        shift[j] = beta[c] - mean * sc;
    }

    #pragma unroll
    for (int r = 0; r < 4; r++) {
        int row = rowBase + ty * 4 + r;
        if (row < n) {
            float4 yv = ((const float4*)(y2 + (size_t)row * 64))[tx];
            float o0 = acc[r].x + yv.x * scale[0] + shift[0];
            float o1 = acc[r].y + yv.y * scale[1] + shift[1];
            float o2 = acc[r].z + yv.z * scale[2] + shift[2];
            float o3 = acc[r].w + yv.w * scale[3] + shift[3];
            float4 ov;
            ov.x = o0 > 0.f ? o0 : 0.f;
            ov.y = o1 > 0.f ? o1 : 0.f;
            ov.z = o2 > 0.f ? o2 : 0.f;
            ov.w = o3 > 0.f ? o3 : 0.f;
            ((float4*)(out + (size_t)row * 64))[tx] = ov;
        }
    }
}

// ================= host =================
extern "C" void kernel_launch(void* const* d_in, const int* in_sizes, int n_in,
                              void* d_out, int out_size)
{
    const float* u   = (const float*)d_in[0];
    const float* v   = (const float*)d_in[1];
    const int*   es  = (const int*)  d_in[2];
    const int*   ee  = (const int*)  d_in[3];
    const float* Ui1 = (const float*)d_in[4];
    const float* Uj1 = (const float*)d_in[5];
    const float* Vi1 = (const float*)d_in[6];
    const float* Vj1 = (const float*)d_in[7];
    const float* bu1 = (const float*)d_in[8];
    const float* bv1 = (const float*)d_in[9];
    const float* Ui2 = (const float*)d_in[10];
    const float* Uj2 = (const float*)d_in[11];
    const float* Vi2 = (const float*)d_in[12];
    const float* Vj2 = (const float*)d_in[13];
    const float* bu2 = (const float*)d_in[14];
    const float* bv2 = (const float*)d_in[15];
    const float* R   = (const float*)d_in[16];
    const float* gamma1 = (const float*)d_in[17];
    const float* beta1  = (const float*)d_in[18];
    const float* gamma2 = (const float*)d_in[19];
    const float* beta2  = (const float*)d_in[20];

    const int nU = in_sizes[0] / 64;
    const int nV = in_sizes[1] / 64;
    const int n  = nU + nV;
    const int nE = in_sizes[2];

    float *px, *psu, *pxvi, *py, *py2, *pst1, *pst2;
    int *pcnt;
    cudaGetSymbolAddress((void**)&px,   g_x);
    cudaGetSymbolAddress((void**)&psu,  g_su);
    cudaGetSymbolAddress((void**)&pxvi, g_xvi);
    cudaGetSymbolAddress((void**)&py,   g_y);
    cudaGetSymbolAddress((void**)&py2,  g_y2);
    cudaGetSymbolAddress((void**)&pst1, g_stats1);
    cudaGetSymbolAddress((void**)&pst2, g_stats2);
    cudaGetSymbolAddress((void**)&pcnt, g_cnt);

    cudaFuncSetAttribute(gemm4_kernel<false>, cudaFuncAttributeMaxDynamicSharedMemorySize, GEMM4_SMEM);
    cudaFuncSetAttribute(gemm4_kernel<true>,  cudaFuncAttributeMaxDynamicSharedMemorySize, GEMM4_SMEM);

    cudaMemcpyAsync(px,                   u, (size_t)nU * 64 * sizeof(float), cudaMemcpyDeviceToDevice);
    cudaMemcpyAsync(px + (size_t)nU * 64, v, (size_t)nV * 64 * sizeof(float), cudaMemcpyDeviceToDevice);
    cudaMemsetAsync(pcnt, 0, (MAXN + 1) * sizeof(int));
    cudaMemsetAsync(pst1, 0, 2 * D * sizeof(float));
    cudaMemsetAsync(pst2, 0, 2 * D * sizeof(float));

    const int eb = (nE + 255) / 256;
    const int nb = (n + 255) / 256;
    const int gemmBlocks = (n + 63) / 64;
    const int aggBlocks  = (n + 7) / 8;

    hist_kernel<<<eb, 256>>>(ee, nE);
    scan_block_kernel<<<nb, 256>>>(n);
    scan_add_kernel<<<nb, 256>>>(n);

    // ---- stage 1 GEMM (launch #4 — profiled) ----
    gemm4_kernel<false><<<gemmBlocks, 256, GEMM4_SMEM>>>(px, Ui1, Uj1, Vi1, Vj1, bu1, bv1,
                                                         nullptr, nullptr, nullptr,
                                                         psu, py, pxvi, n);
    scatter_kernel<<<eb, 256>>>(es, ee, nE);
    agg_kernel<<<aggBlocks, 256>>>(pxvi, psu, py, pst1, n);

    // ---- stage 2 (BN1+ReLU fused into X load) ----
    gemm4_kernel<true><<<gemmBlocks, 256, GEMM4_SMEM>>>(py, Ui2, Uj2, Vi2, Vj2, bu2, bv2,
                                                        pst1, gamma1, beta1,
                                                        psu, py2, pxvi, n);
    agg_kernel<<<aggBlocks, 256>>>(pxvi, psu, py2, pst2, n);

    // ---- final: relu(BN2(y2) + x_in @ R) ----
    final_kernel<<<gemmBlocks, 256>>>(px, R, py2, pst2, gamma2, beta2, (float*)d_out, n);
}